// round 15
// baseline (speedup 1.0000x reference)
#include <cuda_runtime.h>
#include <math.h>
#include <stdint.h>

// Problem constants
#define Bb 4
#define Ss 1024
#define Ee 1024
#define Hh 16
#define DH 64
#define MROWS (Bb * Ss)      // 4096
#define QKVN (3 * Ee)        // 3072
#define NROWS (Bb * Hh * Ss) // 65536 attention rows
#define NNZ_CAP 16

// Scratch
__device__ float g_qkv[(size_t)MROWS * QKVN];
__device__ float g_P[(size_t)Bb * Hh * Ss * Ss];
__device__ float g_ao[(size_t)MROWS * Ee];
__device__ float g_spill[(size_t)MROWS * Ee];

// ---------------------------------------------------------------------------
// Common helpers
// ---------------------------------------------------------------------------
__device__ __forceinline__ unsigned f2tf32_rna(float x) {
    unsigned u;
    asm("cvt.rna.tf32.f32 %0, %1;" : "=r"(u) : "f"(x));
    return u;
}

__device__ __forceinline__ void split3(float x, unsigned& h, unsigned& l) {
    unsigned hu = __float_as_uint(x) & 0xffffe000u;  // truncate
    h = hu;
    l = __float_as_uint(x - __uint_as_float(hu));    // residual
}

#define MMA_TF32(cc, aa, bb)                                              \
    asm volatile(                                                          \
        "mma.sync.aligned.m16n8k8.row.col.f32.tf32.tf32.f32 "             \
        "{%0,%1,%2,%3}, {%4,%5,%6,%7}, {%8,%9}, {%0,%1,%2,%3};"           \
        : "+f"(cc[0]), "+f"(cc[1]), "+f"(cc[2]), "+f"(cc[3])              \
        : "r"(aa[0]), "r"(aa[1]), "r"(aa[2]), "r"(aa[3]),                 \
          "r"(bb[0]), "r"(bb[1]))

#define CP_ASYNC16(dst, src)                                              \
    asm volatile("cp.async.cg.shared.global [%0], [%1], 16;"              \
                 :: "r"(dst), "l"(src))
#define CP_COMMIT() asm volatile("cp.async.commit_group;")
#define CP_WAIT_ALL() asm volatile("cp.async.wait_group 0;")
#define CP_WAIT1() asm volatile("cp.async.wait_group 1;")

// Tiles
#define ASTR 36
#define G1_A_TILE (128 * ASTR)        // 4608 floats
#define G1_BT_TILE (128 * ASTR)       // 4608
#define G1_BN_TILE (32 * 128)         // 4096
#define G1_SMEM_T (3 * (G1_A_TILE + G1_BT_TILE))   // 110592 B
#define G1_SMEM_N (3 * (G1_A_TILE + G1_BN_TILE))   // 104448 B
#define X1_SMEM   (2 * (G1_A_TILE + G1_BN_TILE) * 4)  // 69632 B (2-stage)

template <int TRANSB>
__device__ __forceinline__ void g1_load(
    const float* __restrict__ Abase, const float* __restrict__ Bbase,
    int lda, int ldb, int k0, float* As, float* Bs, int tid)
{
    {
        const int row = tid >> 3;
        const int col = (tid & 7) * 4;
        const float* src = Abase + (size_t)row * lda + k0 + col;
        unsigned dst = (unsigned)__cvta_generic_to_shared(As + row * ASTR + col);
        #pragma unroll
        for (int r = 0; r < 8; ++r)
            CP_ASYNC16(dst + r * 16 * ASTR * 4, src + (size_t)r * 16 * lda);
    }
    if (TRANSB) {
        const int row = tid >> 3;
        const int col = (tid & 7) * 4;
        const float* src = Bbase + (size_t)row * ldb + k0 + col;
        unsigned dst = (unsigned)__cvta_generic_to_shared(Bs + row * ASTR + col);
        #pragma unroll
        for (int r = 0; r < 8; ++r)
            CP_ASYNC16(dst + r * 16 * ASTR * 4, src + (size_t)r * 16 * ldb);
    } else {
        #pragma unroll
        for (int r = 0; r < 8; ++r) {
            const int elem = r * 128 + tid;
            const int kr = elem >> 5;
            const int c4 = (elem & 31) * 4;
            const float* src = Bbase + (size_t)(k0 + kr) * ldb + c4;
            unsigned dst = (unsigned)__cvta_generic_to_shared(
                Bs + kr * 128 + (c4 ^ (8 * (kr & 3))));
            CP_ASYNC16(dst, src);
        }
    }
}

// ===========================================================================
// x3 mainloop (3-stage, proven): full tf32x3, pass-major MMA order.
// ===========================================================================
template <int TRANSB>
__device__ __forceinline__ void g3_run(
    const float* __restrict__ Abase, const float* __restrict__ Bbase,
    const float* __restrict__ bias, float* __restrict__ Cb,
    int K, int lda, int ldb, int ldc, float alpha,
    float* As, float* Bs, int colBase)
{
    const int B_TILE = TRANSB ? G1_BT_TILE : G1_BN_TILE;
    const int tid = threadIdx.x;
    const int warp = tid >> 5, lane = tid & 31;
    const int wm = warp >> 1, wn = warp & 1;
    const int g = lane >> 2, t = lane & 3;

    float acc[4][8][4];
    #pragma unroll
    for (int mt = 0; mt < 4; ++mt)
        #pragma unroll
        for (int nt = 0; nt < 8; ++nt)
            #pragma unroll
            for (int r = 0; r < 4; ++r) acc[mt][nt][r] = 0.f;

    const int KT = K >> 5;

    g1_load<TRANSB>(Abase, Bbase, lda, ldb, 0, As, Bs, tid);
    CP_COMMIT();
    if (KT > 1) {
        g1_load<TRANSB>(Abase, Bbase, lda, ldb, 32,
                        As + G1_A_TILE, Bs + B_TILE, tid);
        CP_COMMIT();
    }

    for (int kt = 0; kt < KT; ++kt) {
        if (kt < KT - 1) CP_WAIT1(); else CP_WAIT_ALL();
        __syncthreads();

        if (kt + 2 < KT) {
            const int buf = (kt + 2) % 3;
            g1_load<TRANSB>(Abase, Bbase, lda, ldb, (kt + 2) * 32,
                            As + buf * G1_A_TILE, Bs + buf * B_TILE, tid);
            CP_COMMIT();
        }

        const float* Ac = As + (kt % 3) * G1_A_TILE;
        const float* Bc = Bs + (kt % 3) * B_TILE;

        #pragma unroll
        for (int kk = 0; kk < 32; kk += 8) {
            unsigned a_h[4][4], a_l[4][4];
            const int kcol = kk + t;
            #pragma unroll
            for (int mt = 0; mt < 4; ++mt) {
                const int m0 = wm * 64 + mt * 16 + g;
                split3(Ac[m0 * ASTR + kcol],           a_h[mt][0], a_l[mt][0]);
                split3(Ac[(m0 + 8) * ASTR + kcol],     a_h[mt][1], a_l[mt][1]);
                split3(Ac[m0 * ASTR + kcol + 4],       a_h[mt][2], a_l[mt][2]);
                split3(Ac[(m0 + 8) * ASTR + kcol + 4], a_h[mt][3], a_l[mt][3]);
            }
            #pragma unroll
            for (int nt = 0; nt < 8; ++nt) {
                const int n0 = wn * 64 + nt * 8 + g;
                float y0, y1;
                if (TRANSB) {
                    y0 = Bc[n0 * ASTR + kk + t];
                    y1 = Bc[n0 * ASTR + kk + t + 4];
                } else {
                    const int nsw = n0 ^ (8 * t);
                    y0 = Bc[(kk + t) * 128 + nsw];
                    y1 = Bc[(kk + t + 4) * 128 + nsw];
                }
                unsigned b_h[2], b_l[2];
                split3(y0, b_h[0], b_l[0]);
                split3(y1, b_h[1], b_l[1]);
                #pragma unroll
                for (int mt = 0; mt < 4; ++mt)
                    MMA_TF32(acc[mt][nt], a_h[mt], b_h);
                #pragma unroll
                for (int mt = 0; mt < 4; ++mt)
                    MMA_TF32(acc[mt][nt], a_h[mt], b_l);
                #pragma unroll
                for (int mt = 0; mt < 4; ++mt)
                    MMA_TF32(acc[mt][nt], a_l[mt], b_h);
            }
        }
    }

    #pragma unroll
    for (int mt = 0; mt < 4; ++mt) {
        #pragma unroll
        for (int nt = 0; nt < 8; ++nt) {
            const int row0 = blockIdx.y * 128 + wm * 64 + mt * 16 + g;
            const int col  = colBase + wn * 64 + nt * 8 + t * 2;
            float bv0 = 0.f, bv1 = 0.f;
            if (bias) { bv0 = bias[col]; bv1 = bias[col + 1]; }
            float2 v0 = make_float2(acc[mt][nt][0] * alpha + bv0,
                                    acc[mt][nt][1] * alpha + bv1);
            *(float2*)(Cb + (size_t)row0 * ldc + col) = v0;
            float2 v1 = make_float2(acc[mt][nt][2] * alpha + bv0,
                                    acc[mt][nt][3] * alpha + bv1);
            *(float2*)(Cb + (size_t)(row0 + 8) * ldc + col) = v1;
        }
    }
}

// ---------------------------------------------------------------------------
// QK projection: x @ w_qkv[:, :2048] + bias (tf32x3)
// ---------------------------------------------------------------------------
__global__ __launch_bounds__(128) void gemm_qk3_kernel(
    const float* __restrict__ A, const float* __restrict__ B,
    const float* __restrict__ bias, float* __restrict__ C)
{
    extern __shared__ float sm[];
    float* As = sm;
    float* Bs = sm + 3 * G1_A_TILE;
    const float* Abase = A + (size_t)blockIdx.y * 128 * Ee;
    const float* Bbase = B + blockIdx.x * 128;
    g3_run<0>(Abase, Bbase, bias, C, Ee, Ee, QKVN, QKVN, 1.0f,
              As, Bs, blockIdx.x * 128);
}

// ---------------------------------------------------------------------------
// QK^T: per (b,h), transB, tf32x3
// ---------------------------------------------------------------------------
__global__ __launch_bounds__(128) void gemm_qkt_kernel(
    const float* __restrict__ qkv, float* __restrict__ P)
{
    extern __shared__ float sm[];
    float* As = sm;
    float* Bs = sm + 3 * G1_A_TILE;

    const int z = blockIdx.z;
    const int b = z >> 4, h = z & 15;
    const float* Ab  = qkv + (size_t)b * Ss * QKVN + h * DH;
    const float* Bbp = qkv + (size_t)b * Ss * QKVN + Ee + h * DH;
    float* Cb = P + (size_t)z * Ss * Ss;

    const float* Abase = Ab + (size_t)blockIdx.y * 128 * QKVN;
    const float* Bbase = Bbp + (size_t)blockIdx.x * 128 * QKVN;

    g3_run<1>(Abase, Bbase, nullptr, Cb, DH, QKVN, QKVN, Ss, 0.125f,
              As, Bs, blockIdx.x * 128);
}

// ===========================================================================
// Lightweight x1 GEMM: 2-stage pipeline, reg-capped for 3 CTAs/SM.
// Buffer for tile kt+2 is the one read at kt -> load issued AFTER compute
// plus a second barrier (no read/write race).
// ===========================================================================
__global__ __launch_bounds__(128, 3) void gemm_x1l_kernel(
    const float* __restrict__ A, const float* __restrict__ B,
    const float* __restrict__ bias, float* __restrict__ C,
    int K, int lda, int ldb, int ldc)
{
    extern __shared__ float sm[];
    float* As = sm;                       // 2 stages
    float* Bs = sm + 2 * G1_A_TILE;       // 2 stages

    const int tid = threadIdx.x;
    const float* Abase = A + (size_t)blockIdx.y * 128 * lda;
    const float* Bbase = B + blockIdx.x * 128;

    const int warp = tid >> 5, lane = tid & 31;
    const int wm = warp >> 1, wn = warp & 1;
    const int g = lane >> 2, t = lane & 3;

    float acc[4][8][4];
    #pragma unroll
    for (int mt = 0; mt < 4; ++mt)
        #pragma unroll
        for (int nt = 0; nt < 8; ++nt)
            #pragma unroll
            for (int r = 0; r < 4; ++r) acc[mt][nt][r] = 0.f;

    const int KT = K >> 5;

    g1_load<0>(Abase, Bbase, lda, ldb, 0, As, Bs, tid);
    CP_COMMIT();
    if (KT > 1) {
        g1_load<0>(Abase, Bbase, lda, ldb, 32,
                   As + G1_A_TILE, Bs + G1_BN_TILE, tid);
        CP_COMMIT();
    }

    for (int kt = 0; kt < KT; ++kt) {
        if (kt < KT - 1) CP_WAIT1(); else CP_WAIT_ALL();
        __syncthreads();

        const float* Ac = As + (kt & 1) * G1_A_TILE;
        const float* Bc = Bs + (kt & 1) * G1_BN_TILE;

        #pragma unroll
        for (int kk = 0; kk < 32; kk += 8) {
            unsigned a_h[4][4];
            const int kcol = kk + t;
            #pragma unroll
            for (int mt = 0; mt < 4; ++mt) {
                const int m0 = wm * 64 + mt * 16 + g;
                a_h[mt][0] = f2tf32_rna(Ac[m0 * ASTR + kcol]);
                a_h[mt][1] = f2tf32_rna(Ac[(m0 + 8) * ASTR + kcol]);
                a_h[mt][2] = f2tf32_rna(Ac[m0 * ASTR + kcol + 4]);
                a_h[mt][3] = f2tf32_rna(Ac[(m0 + 8) * ASTR + kcol + 4]);
            }
            #pragma unroll
            for (int nt = 0; nt < 8; ++nt) {
                const int n0 = wn * 64 + nt * 8 + g;
                const int nsw = n0 ^ (8 * t);
                unsigned b_h[2];
                b_h[0] = f2tf32_rna(Bc[(kk + t) * 128 + nsw]);
                b_h[1] = f2tf32_rna(Bc[(kk + t + 4) * 128 + nsw]);
                #pragma unroll
                for (int mt = 0; mt < 4; ++mt)
                    MMA_TF32(acc[mt][nt], a_h[mt], b_h);
            }
        }

        if (kt + 2 < KT) {
            __syncthreads();   // all warps done reading buffer (kt&1)
            g1_load<0>(Abase, Bbase, lda, ldb, (kt + 2) * 32,
                       As + (kt & 1) * G1_A_TILE,
                       Bs + (kt & 1) * G1_BN_TILE, tid);
            CP_COMMIT();
        }
    }

    #pragma unroll
    for (int mt = 0; mt < 4; ++mt) {
        #pragma unroll
        for (int nt = 0; nt < 8; ++nt) {
            const int row0 = blockIdx.y * 128 + wm * 64 + mt * 16 + g;
            const int col  = blockIdx.x * 128 + wn * 64 + nt * 8 + t * 2;
            float bv0 = bias[col], bv1 = bias[col + 1];
            float2 v0 = make_float2(acc[mt][nt][0] + bv0,
                                    acc[mt][nt][1] + bv1);
            *(float2*)(C + (size_t)row0 * ldc + col) = v0;
            float2 v1 = make_float2(acc[mt][nt][2] + bv0,
                                    acc[mt][nt][3] + bv1);
            *(float2*)(C + (size_t)(row0 + 8) * ldc + col) = v1;
        }
    }
}

// ---------------------------------------------------------------------------
// Warp-per-row softmax + threshold mask + renorm + FUSED sparse AV (proven).
// ---------------------------------------------------------------------------
__global__ __launch_bounds__(256) void softmax_av_kernel(
    float* __restrict__ P, const float* __restrict__ qkv,
    float* __restrict__ ao)
{
    __shared__ int   s_i[8][NNZ_CAP];
    __shared__ float s_v[8][NNZ_CAP];

    const int w = threadIdx.x >> 5;
    const int r = blockIdx.x * 8 + w;
    const int lane = threadIdx.x & 31;
    float* Pr = P + (size_t)r * Ss;

    float l[32];
    #pragma unroll
    for (int it = 0; it < 8; ++it) {
        float4 v = __ldcs((const float4*)(Pr + it * 128 + lane * 4));
        l[it * 4 + 0] = v.x; l[it * 4 + 1] = v.y;
        l[it * 4 + 2] = v.z; l[it * 4 + 3] = v.w;
    }

    float m = l[0]; int mi = lane * 4;
    #pragma unroll
    for (int it = 0; it < 8; ++it)
        #pragma unroll
        for (int j = 0; j < 4; ++j) {
            const int col = it * 128 + lane * 4 + j;
            if (l[it * 4 + j] > m || (l[it * 4 + j] == m && col < mi)) {
                m = l[it * 4 + j]; mi = col;
            }
        }
    #pragma unroll
    for (int o = 16; o > 0; o >>= 1) {
        float ov = __shfl_xor_sync(0xffffffffu, m, o);
        int   oi = __shfl_xor_sync(0xffffffffu, mi, o);
        if (ov > m || (ov == m && oi < mi)) { m = ov; mi = oi; }
    }

    float zs = 0.f;
    #pragma unroll
    for (int i = 0; i < 32; ++i) { l[i] = __expf(l[i] - m); zs += l[i]; }
    #pragma unroll
    for (int o = 16; o > 0; o >>= 1) zs += __shfl_xor_sync(0xffffffffu, zs, o);
    const float invZ = 1.0f / zs;

    float ms = 0.f; int cl = 0;
    #pragma unroll
    for (int i = 0; i < 32; ++i) {
        l[i] *= invZ;
        if (l[i] > 0.1f) { ms += l[i]; ++cl; }
    }
    #pragma unroll
    for (int o = 16; o > 0; o >>= 1) ms += __shfl_xor_sync(0xffffffffu, ms, o);

    int inc = cl;
    #pragma unroll
    for (int o = 1; o < 32; o <<= 1) {
        int n = __shfl_up_sync(0xffffffffu, inc, o);
        if (lane >= o) inc += n;
    }
    const int excl = inc - cl;
    const int total = __shfl_sync(0xffffffffu, inc, 31);

    if (total > 0) {
        const float inv = 1.0f / ms;
        int pos = excl;
        #pragma unroll
        for (int it = 0; it < 8; ++it) {
            float4 o4;
            float q[4];
            #pragma unroll
            for (int j = 0; j < 4; ++j) {
                const float p = l[it * 4 + j];
                const bool sel = p > 0.1f;
                q[j] = sel ? p * inv : 0.f;
                if (sel) {
                    if (pos < NNZ_CAP) {
                        s_i[w][pos] = it * 128 + lane * 4 + j;
                        s_v[w][pos] = q[j];
                    }
                    ++pos;
                }
            }
            o4.x = q[0]; o4.y = q[1]; o4.z = q[2]; o4.w = q[3];
            __stcs((float4*)(Pr + it * 128 + lane * 4), o4);
        }
    } else {
        #pragma unroll
        for (int it = 0; it < 8; ++it) {
            float4 o4;
            #pragma unroll
            for (int j = 0; j < 4; ++j) {
                const int col = it * 128 + lane * 4 + j;
                ((float*)&o4)[j] = (col == mi) ? 1.f : 0.f;
            }
            __stcs((float4*)(Pr + it * 128 + lane * 4), o4);
        }
        if (lane == 0) {
            s_i[w][0] = mi;
            s_v[w][0] = 1.0f;
        }
    }
    __syncwarp();

    const int cnt0 = (total > 0) ? total : 1;
    const int cnt = (cnt0 < NNZ_CAP) ? cnt0 : NNZ_CAP;

    const int bh = r >> 10, i = r & 1023;
    const int b = bh >> 4, h = bh & 15;
    const float* Vb = qkv + (size_t)b * Ss * QKVN + 2 * Ee + h * DH;

    float a0 = 0.f, a1 = 0.f;
    for (int k = 0; k < cnt; ++k) {
        const int j = s_i[w][k];
        const float v = s_v[w][k];
        const float* Vr = Vb + (size_t)j * QKVN;
        a0 += v * Vr[lane];
        a1 += v * Vr[lane + 32];
    }
    float* Or = ao + (size_t)(b * Ss + i) * Ee + h * DH;
    Or[lane] = a0;
    Or[lane + 32] = a1;
}

// ---------------------------------------------------------------------------
// Launch
// ---------------------------------------------------------------------------
static float* sym_addr(const void* sym)
{
    void* p = nullptr;
    cudaGetSymbolAddress(&p, sym);
    return (float*)p;
}

extern "C" void kernel_launch(void* const* d_in, const int* in_sizes, int n_in,
                              void* d_out, int out_size)
{
    const float* x      = (const float*)d_in[0];
    const float* w_qkv  = (const float*)d_in[1];
    const float* b_qkv  = (const float*)d_in[2];
    const float* w_proj = (const float*)d_in[3];
    const float* b_proj = (const float*)d_in[4];

    float* qkv = sym_addr(g_qkv);
    float* ao  = sym_addr(g_ao);

    const size_t OUT_N  = (size_t)Bb * Ss * Ee;
    const size_t ATTN_N = (size_t)Bb * Hh * Ss * Ss;

    float* out = (float*)d_out;
    float* P;
    float* mainOut;
    if ((size_t)out_size >= OUT_N + ATTN_N) {
        mainOut = out;
        P = out + OUT_N;
    } else if ((size_t)out_size == ATTN_N) {
        mainOut = sym_addr(g_spill);
        P = out;
    } else {
        mainOut = out;
        P = sym_addr(g_P);
    }

    const int smemN = G1_SMEM_N * sizeof(float);   // 104448
    const int smemT = G1_SMEM_T * sizeof(float);   // 110592
    cudaFuncSetAttribute(gemm_qk3_kernel,
                         cudaFuncAttributeMaxDynamicSharedMemorySize, smemN);
    cudaFuncSetAttribute(gemm_qkt_kernel,
                         cudaFuncAttributeMaxDynamicSharedMemorySize, smemT);
    cudaFuncSetAttribute(gemm_x1l_kernel,
                         cudaFuncAttributeMaxDynamicSharedMemorySize, X1_SMEM);

    // 1. QK projection: [4096,1024] @ [1024,2048] + bias (tf32x3 — feeds mask)
    {
        dim3 grid(2048 / 128, MROWS / 128, 1);
        gemm_qk3_kernel<<<grid, 128, smemN>>>(x, w_qkv, b_qkv, qkv);
    }
    // 2. V projection: [4096,1024] @ [1024,1024] + bias (tf32x1, light)
    {
        dim3 grid(1024 / 128, MROWS / 128, 1);
        gemm_x1l_kernel<<<grid, 128, X1_SMEM>>>(
            x, w_qkv + 2048, b_qkv + 2048, qkv + 2048, Ee, Ee, QKVN, QKVN);
    }
    // 3. QK^T logits per (b,h), alpha = Dh^-0.5 (tf32x3)
    {
        dim3 grid(Ss / 128, Ss / 128, Bb * Hh);
        gemm_qkt_kernel<<<grid, 128, smemT>>>(qkv, P);
    }
    // 4. warp-per-row softmax + mask + renorm + fused sparse AV
    softmax_av_kernel<<<NROWS / 8, 256>>>(P, qkv, ao);
    // 5. output projection: [4096,1024] @ [1024,1024] + bias (tf32x1, light)
    {
        dim3 grid(Ee / 128, MROWS / 128, 1);
        gemm_x1l_kernel<<<grid, 128, X1_SMEM>>>(
            ao, w_proj, b_proj, mainOut, Ee, Ee, Ee, Ee);
    }
}

// round 16
// speedup vs baseline: 1.0427x; 1.0427x over previous
#include <cuda_runtime.h>
#include <math.h>
#include <stdint.h>

// Problem constants
#define Bb 4
#define Ss 1024
#define Ee 1024
#define Hh 16
#define DH 64
#define MROWS (Bb * Ss)      // 4096
#define QKVN (3 * Ee)        // 3072
#define NROWS (Bb * Hh * Ss) // 65536 attention rows
#define NNZ_CAP 16

// Scratch
__device__ float g_qkv[(size_t)MROWS * QKVN];
__device__ float g_P[(size_t)Bb * Hh * Ss * Ss];
__device__ float g_ao[(size_t)MROWS * Ee];
__device__ float g_spill[(size_t)MROWS * Ee];

// ---------------------------------------------------------------------------
// Common helpers
// ---------------------------------------------------------------------------
__device__ __forceinline__ unsigned f2tf32_rna(float x) {
    unsigned u;
    asm("cvt.rna.tf32.f32 %0, %1;" : "=r"(u) : "f"(x));
    return u;
}

__device__ __forceinline__ void split3(float x, unsigned& h, unsigned& l) {
    unsigned hu = __float_as_uint(x) & 0xffffe000u;  // truncate
    h = hu;
    l = __float_as_uint(x - __uint_as_float(hu));    // residual
}

#define MMA_TF32(cc, aa, bb)                                              \
    asm volatile(                                                          \
        "mma.sync.aligned.m16n8k8.row.col.f32.tf32.tf32.f32 "             \
        "{%0,%1,%2,%3}, {%4,%5,%6,%7}, {%8,%9}, {%0,%1,%2,%3};"           \
        : "+f"(cc[0]), "+f"(cc[1]), "+f"(cc[2]), "+f"(cc[3])              \
        : "r"(aa[0]), "r"(aa[1]), "r"(aa[2]), "r"(aa[3]),                 \
          "r"(bb[0]), "r"(bb[1]))

#define CP_ASYNC16(dst, src)                                              \
    asm volatile("cp.async.cg.shared.global [%0], [%1], 16;"              \
                 :: "r"(dst), "l"(src))
#define CP_COMMIT() asm volatile("cp.async.commit_group;")
#define CP_WAIT_ALL() asm volatile("cp.async.wait_group 0;")
#define CP_WAIT1() asm volatile("cp.async.wait_group 1;")

// Tiles
#define ASTR 36
#define G1_A_TILE (128 * ASTR)        // 4608 floats
#define G1_BT_TILE (128 * ASTR)       // 4608
#define G1_BN_TILE (32 * 128)         // 4096
#define G1_SMEM_T (3 * (G1_A_TILE + G1_BT_TILE))   // 110592 B
#define G1_SMEM_N (3 * (G1_A_TILE + G1_BN_TILE))   // 104448 B

// ---------------------------------------------------------------------------
// 128-thread tile loader (x3 kernels)
// ---------------------------------------------------------------------------
template <int TRANSB>
__device__ __forceinline__ void g1_load(
    const float* __restrict__ Abase, const float* __restrict__ Bbase,
    int lda, int ldb, int k0, float* As, float* Bs, int tid)
{
    {
        const int row = tid >> 3;
        const int col = (tid & 7) * 4;
        const float* src = Abase + (size_t)row * lda + k0 + col;
        unsigned dst = (unsigned)__cvta_generic_to_shared(As + row * ASTR + col);
        #pragma unroll
        for (int r = 0; r < 8; ++r)
            CP_ASYNC16(dst + r * 16 * ASTR * 4, src + (size_t)r * 16 * lda);
    }
    if (TRANSB) {
        const int row = tid >> 3;
        const int col = (tid & 7) * 4;
        const float* src = Bbase + (size_t)row * ldb + k0 + col;
        unsigned dst = (unsigned)__cvta_generic_to_shared(Bs + row * ASTR + col);
        #pragma unroll
        for (int r = 0; r < 8; ++r)
            CP_ASYNC16(dst + r * 16 * ASTR * 4, src + (size_t)r * 16 * ldb);
    } else {
        #pragma unroll
        for (int r = 0; r < 8; ++r) {
            const int elem = r * 128 + tid;
            const int kr = elem >> 5;
            const int c4 = (elem & 31) * 4;
            const float* src = Bbase + (size_t)(k0 + kr) * ldb + c4;
            unsigned dst = (unsigned)__cvta_generic_to_shared(
                Bs + kr * 128 + (c4 ^ (8 * (kr & 3))));
            CP_ASYNC16(dst, src);
        }
    }
}

// ---------------------------------------------------------------------------
// 256-thread tile loader (x1 kernels; round-4 proven layout)
// ---------------------------------------------------------------------------
__device__ __forceinline__ void g2_load(
    const float* __restrict__ Abase, const float* __restrict__ Bbase,
    int lda, int ldb, int k0, float* As, float* Bs, int tid)
{
    {
        const int row = tid >> 3;               // 0..31
        const int col = (tid & 7) * 4;
        const float* src = Abase + (size_t)row * lda + k0 + col;
        unsigned dst = (unsigned)__cvta_generic_to_shared(As + row * ASTR + col);
        #pragma unroll
        for (int r = 0; r < 4; ++r)
            CP_ASYNC16(dst + r * 32 * ASTR * 4, src + (size_t)r * 32 * lda);
    }
    #pragma unroll
    for (int r = 0; r < 4; ++r) {
        const int elem = r * 256 + tid;
        const int kr = elem >> 5;
        const int c4 = (elem & 31) * 4;
        const float* src = Bbase + (size_t)(k0 + kr) * ldb + c4;
        unsigned dst = (unsigned)__cvta_generic_to_shared(
            Bs + kr * 128 + (c4 ^ (8 * (kr & 3))));
        CP_ASYNC16(dst, src);
    }
}

// ===========================================================================
// x3 mainloop (128 threads, 2x2 warps, 64x64 warp tile, 3-stage, pass-major)
// ===========================================================================
template <int TRANSB>
__device__ __forceinline__ void g3_run(
    const float* __restrict__ Abase, const float* __restrict__ Bbase,
    const float* __restrict__ bias, float* __restrict__ Cb,
    int K, int lda, int ldb, int ldc, float alpha,
    float* As, float* Bs, int colBase)
{
    const int B_TILE = TRANSB ? G1_BT_TILE : G1_BN_TILE;
    const int tid = threadIdx.x;
    const int warp = tid >> 5, lane = tid & 31;
    const int wm = warp >> 1, wn = warp & 1;
    const int g = lane >> 2, t = lane & 3;

    float acc[4][8][4];
    #pragma unroll
    for (int mt = 0; mt < 4; ++mt)
        #pragma unroll
        for (int nt = 0; nt < 8; ++nt)
            #pragma unroll
            for (int r = 0; r < 4; ++r) acc[mt][nt][r] = 0.f;

    const int KT = K >> 5;

    g1_load<TRANSB>(Abase, Bbase, lda, ldb, 0, As, Bs, tid);
    CP_COMMIT();
    if (KT > 1) {
        g1_load<TRANSB>(Abase, Bbase, lda, ldb, 32,
                        As + G1_A_TILE, Bs + B_TILE, tid);
        CP_COMMIT();
    }

    for (int kt = 0; kt < KT; ++kt) {
        if (kt < KT - 1) CP_WAIT1(); else CP_WAIT_ALL();
        __syncthreads();

        if (kt + 2 < KT) {
            const int buf = (kt + 2) % 3;
            g1_load<TRANSB>(Abase, Bbase, lda, ldb, (kt + 2) * 32,
                            As + buf * G1_A_TILE, Bs + buf * B_TILE, tid);
            CP_COMMIT();
        }

        const float* Ac = As + (kt % 3) * G1_A_TILE;
        const float* Bc = Bs + (kt % 3) * B_TILE;

        #pragma unroll
        for (int kk = 0; kk < 32; kk += 8) {
            unsigned a_h[4][4], a_l[4][4];
            const int kcol = kk + t;
            #pragma unroll
            for (int mt = 0; mt < 4; ++mt) {
                const int m0 = wm * 64 + mt * 16 + g;
                split3(Ac[m0 * ASTR + kcol],           a_h[mt][0], a_l[mt][0]);
                split3(Ac[(m0 + 8) * ASTR + kcol],     a_h[mt][1], a_l[mt][1]);
                split3(Ac[m0 * ASTR + kcol + 4],       a_h[mt][2], a_l[mt][2]);
                split3(Ac[(m0 + 8) * ASTR + kcol + 4], a_h[mt][3], a_l[mt][3]);
            }
            #pragma unroll
            for (int nt = 0; nt < 8; ++nt) {
                const int n0 = wn * 64 + nt * 8 + g;
                float y0, y1;
                if (TRANSB) {
                    y0 = Bc[n0 * ASTR + kk + t];
                    y1 = Bc[n0 * ASTR + kk + t + 4];
                } else {
                    const int nsw = n0 ^ (8 * t);
                    y0 = Bc[(kk + t) * 128 + nsw];
                    y1 = Bc[(kk + t + 4) * 128 + nsw];
                }
                unsigned b_h[2], b_l[2];
                split3(y0, b_h[0], b_l[0]);
                split3(y1, b_h[1], b_l[1]);
                #pragma unroll
                for (int mt = 0; mt < 4; ++mt)
                    MMA_TF32(acc[mt][nt], a_h[mt], b_h);
                #pragma unroll
                for (int mt = 0; mt < 4; ++mt)
                    MMA_TF32(acc[mt][nt], a_h[mt], b_l);
                #pragma unroll
                for (int mt = 0; mt < 4; ++mt)
                    MMA_TF32(acc[mt][nt], a_l[mt], b_h);
            }
        }
    }

    #pragma unroll
    for (int mt = 0; mt < 4; ++mt) {
        #pragma unroll
        for (int nt = 0; nt < 8; ++nt) {
            const int row0 = blockIdx.y * 128 + wm * 64 + mt * 16 + g;
            const int col  = colBase + wn * 64 + nt * 8 + t * 2;
            float bv0 = 0.f, bv1 = 0.f;
            if (bias) { bv0 = bias[col]; bv1 = bias[col + 1]; }
            float2 v0 = make_float2(acc[mt][nt][0] * alpha + bv0,
                                    acc[mt][nt][1] * alpha + bv1);
            *(float2*)(Cb + (size_t)row0 * ldc + col) = v0;
            float2 v1 = make_float2(acc[mt][nt][2] * alpha + bv0,
                                    acc[mt][nt][3] * alpha + bv1);
            *(float2*)(Cb + (size_t)(row0 + 8) * ldc + col) = v1;
        }
    }
}

// ---------------------------------------------------------------------------
// QK projection: x @ w_qkv[:, :2048] + bias (tf32x3)
// ---------------------------------------------------------------------------
__global__ __launch_bounds__(128) void gemm_qk3_kernel(
    const float* __restrict__ A, const float* __restrict__ B,
    const float* __restrict__ bias, float* __restrict__ C)
{
    extern __shared__ float sm[];
    float* As = sm;
    float* Bs = sm + 3 * G1_A_TILE;
    const float* Abase = A + (size_t)blockIdx.y * 128 * Ee;
    const float* Bbase = B + blockIdx.x * 128;
    g3_run<0>(Abase, Bbase, bias, C, Ee, Ee, QKVN, QKVN, 1.0f,
              As, Bs, blockIdx.x * 128);
}

// ---------------------------------------------------------------------------
// QK^T: per (b,h), transB, tf32x3
// ---------------------------------------------------------------------------
__global__ __launch_bounds__(128) void gemm_qkt_kernel(
    const float* __restrict__ qkv, float* __restrict__ P)
{
    extern __shared__ float sm[];
    float* As = sm;
    float* Bs = sm + 3 * G1_A_TILE;

    const int z = blockIdx.z;
    const int b = z >> 4, h = z & 15;
    const float* Ab  = qkv + (size_t)b * Ss * QKVN + h * DH;
    const float* Bbp = qkv + (size_t)b * Ss * QKVN + Ee + h * DH;
    float* Cb = P + (size_t)z * Ss * Ss;

    const float* Abase = Ab + (size_t)blockIdx.y * 128 * QKVN;
    const float* Bbase = Bbp + (size_t)blockIdx.x * 128 * QKVN;

    g3_run<1>(Abase, Bbase, nullptr, Cb, DH, QKVN, QKVN, Ss, 0.125f,
              As, Bs, blockIdx.x * 128);
}

// ===========================================================================
// x1 GEMM: 256 threads, 8 warps (4x2), warp tile 32x64, 3-stage pipeline.
// Small accumulator (64 fl/thread) -> ~120 regs -> 2 CTAs/SM = 16 warps/SM.
// ===========================================================================
__global__ __launch_bounds__(256) void gemm_x1_kernel(
    const float* __restrict__ A, const float* __restrict__ B,
    const float* __restrict__ bias, float* __restrict__ C,
    int K, int lda, int ldb, int ldc)
{
    extern __shared__ float sm[];
    float* As = sm;
    float* Bs = sm + 3 * G1_A_TILE;

    const int tid = threadIdx.x;
    const float* Abase = A + (size_t)blockIdx.y * 128 * lda;
    const float* Bbase = B + blockIdx.x * 128;

    const int warp = tid >> 5, lane = tid & 31;
    const int wm = warp >> 1, wn = warp & 1;      // 4x2 warps, warp 32x64
    const int g = lane >> 2, t = lane & 3;

    float acc[2][8][4];
    #pragma unroll
    for (int mt = 0; mt < 2; ++mt)
        #pragma unroll
        for (int nt = 0; nt < 8; ++nt)
            #pragma unroll
            for (int r = 0; r < 4; ++r) acc[mt][nt][r] = 0.f;

    const int KT = K >> 5;

    g2_load(Abase, Bbase, lda, ldb, 0, As, Bs, tid);
    CP_COMMIT();
    if (KT > 1) {
        g2_load(Abase, Bbase, lda, ldb, 32,
                As + G1_A_TILE, Bs + G1_BN_TILE, tid);
        CP_COMMIT();
    }

    for (int kt = 0; kt < KT; ++kt) {
        if (kt < KT - 1) CP_WAIT1(); else CP_WAIT_ALL();
        __syncthreads();

        if (kt + 2 < KT) {
            const int buf = (kt + 2) % 3;
            g2_load(Abase, Bbase, lda, ldb, (kt + 2) * 32,
                    As + buf * G1_A_TILE, Bs + buf * G1_BN_TILE, tid);
            CP_COMMIT();
        }

        const float* Ac = As + (kt % 3) * G1_A_TILE;
        const float* Bc = Bs + (kt % 3) * G1_BN_TILE;

        #pragma unroll
        for (int kk = 0; kk < 32; kk += 8) {
            unsigned a_h[2][4];
            const int kcol = kk + t;
            #pragma unroll
            for (int mt = 0; mt < 2; ++mt) {
                const int m0 = wm * 32 + mt * 16 + g;
                a_h[mt][0] = f2tf32_rna(Ac[m0 * ASTR + kcol]);
                a_h[mt][1] = f2tf32_rna(Ac[(m0 + 8) * ASTR + kcol]);
                a_h[mt][2] = f2tf32_rna(Ac[m0 * ASTR + kcol + 4]);
                a_h[mt][3] = f2tf32_rna(Ac[(m0 + 8) * ASTR + kcol + 4]);
            }
            #pragma unroll
            for (int nt = 0; nt < 8; ++nt) {
                const int n0 = wn * 64 + nt * 8 + g;
                const int nsw = n0 ^ (8 * t);
                unsigned b_h[2];
                b_h[0] = f2tf32_rna(Bc[(kk + t) * 128 + nsw]);
                b_h[1] = f2tf32_rna(Bc[(kk + t + 4) * 128 + nsw]);
                #pragma unroll
                for (int mt = 0; mt < 2; ++mt)
                    MMA_TF32(acc[mt][nt], a_h[mt], b_h);
            }
        }
    }

    #pragma unroll
    for (int mt = 0; mt < 2; ++mt) {
        #pragma unroll
        for (int nt = 0; nt < 8; ++nt) {
            const int row0 = blockIdx.y * 128 + wm * 32 + mt * 16 + g;
            const int col  = blockIdx.x * 128 + wn * 64 + nt * 8 + t * 2;
            float bv0 = bias[col], bv1 = bias[col + 1];
            float2 v0 = make_float2(acc[mt][nt][0] + bv0,
                                    acc[mt][nt][1] + bv1);
            *(float2*)(C + (size_t)row0 * ldc + col) = v0;
            float2 v1 = make_float2(acc[mt][nt][2] + bv0,
                                    acc[mt][nt][3] + bv1);
            *(float2*)(C + (size_t)(row0 + 8) * ldc + col) = v1;
        }
    }
}

// ---------------------------------------------------------------------------
// Warp-per-row softmax + threshold mask + renorm + FUSED sparse AV (proven).
// ---------------------------------------------------------------------------
__global__ __launch_bounds__(256) void softmax_av_kernel(
    float* __restrict__ P, const float* __restrict__ qkv,
    float* __restrict__ ao)
{
    __shared__ int   s_i[8][NNZ_CAP];
    __shared__ float s_v[8][NNZ_CAP];

    const int w = threadIdx.x >> 5;
    const int r = blockIdx.x * 8 + w;
    const int lane = threadIdx.x & 31;
    float* Pr = P + (size_t)r * Ss;

    float l[32];
    #pragma unroll
    for (int it = 0; it < 8; ++it) {
        float4 v = __ldcs((const float4*)(Pr + it * 128 + lane * 4));
        l[it * 4 + 0] = v.x; l[it * 4 + 1] = v.y;
        l[it * 4 + 2] = v.z; l[it * 4 + 3] = v.w;
    }

    float m = l[0]; int mi = lane * 4;
    #pragma unroll
    for (int it = 0; it < 8; ++it)
        #pragma unroll
        for (int j = 0; j < 4; ++j) {
            const int col = it * 128 + lane * 4 + j;
            if (l[it * 4 + j] > m || (l[it * 4 + j] == m && col < mi)) {
                m = l[it * 4 + j]; mi = col;
            }
        }
    #pragma unroll
    for (int o = 16; o > 0; o >>= 1) {
        float ov = __shfl_xor_sync(0xffffffffu, m, o);
        int   oi = __shfl_xor_sync(0xffffffffu, mi, o);
        if (ov > m || (ov == m && oi < mi)) { m = ov; mi = oi; }
    }

    float zs = 0.f;
    #pragma unroll
    for (int i = 0; i < 32; ++i) { l[i] = __expf(l[i] - m); zs += l[i]; }
    #pragma unroll
    for (int o = 16; o > 0; o >>= 1) zs += __shfl_xor_sync(0xffffffffu, zs, o);
    const float invZ = 1.0f / zs;

    float ms = 0.f; int cl = 0;
    #pragma unroll
    for (int i = 0; i < 32; ++i) {
        l[i] *= invZ;
        if (l[i] > 0.1f) { ms += l[i]; ++cl; }
    }
    #pragma unroll
    for (int o = 16; o > 0; o >>= 1) ms += __shfl_xor_sync(0xffffffffu, ms, o);

    int inc = cl;
    #pragma unroll
    for (int o = 1; o < 32; o <<= 1) {
        int n = __shfl_up_sync(0xffffffffu, inc, o);
        if (lane >= o) inc += n;
    }
    const int excl = inc - cl;
    const int total = __shfl_sync(0xffffffffu, inc, 31);

    if (total > 0) {
        const float inv = 1.0f / ms;
        int pos = excl;
        #pragma unroll
        for (int it = 0; it < 8; ++it) {
            float4 o4;
            float q[4];
            #pragma unroll
            for (int j = 0; j < 4; ++j) {
                const float p = l[it * 4 + j];
                const bool sel = p > 0.1f;
                q[j] = sel ? p * inv : 0.f;
                if (sel) {
                    if (pos < NNZ_CAP) {
                        s_i[w][pos] = it * 128 + lane * 4 + j;
                        s_v[w][pos] = q[j];
                    }
                    ++pos;
                }
            }
            o4.x = q[0]; o4.y = q[1]; o4.z = q[2]; o4.w = q[3];
            __stcs((float4*)(Pr + it * 128 + lane * 4), o4);
        }
    } else {
        #pragma unroll
        for (int it = 0; it < 8; ++it) {
            float4 o4;
            #pragma unroll
            for (int j = 0; j < 4; ++j) {
                const int col = it * 128 + lane * 4 + j;
                ((float*)&o4)[j] = (col == mi) ? 1.f : 0.f;
            }
            __stcs((float4*)(Pr + it * 128 + lane * 4), o4);
        }
        if (lane == 0) {
            s_i[w][0] = mi;
            s_v[w][0] = 1.0f;
        }
    }
    __syncwarp();

    const int cnt0 = (total > 0) ? total : 1;
    const int cnt = (cnt0 < NNZ_CAP) ? cnt0 : NNZ_CAP;

    const int bh = r >> 10, i = r & 1023;
    const int b = bh >> 4, h = bh & 15;
    const float* Vb = qkv + (size_t)b * Ss * QKVN + 2 * Ee + h * DH;

    float a0 = 0.f, a1 = 0.f;
    for (int k = 0; k < cnt; ++k) {
        const int j = s_i[w][k];
        const float v = s_v[w][k];
        const float* Vr = Vb + (size_t)j * QKVN;
        a0 += v * Vr[lane];
        a1 += v * Vr[lane + 32];
    }
    float* Or = ao + (size_t)(b * Ss + i) * Ee + h * DH;
    Or[lane] = a0;
    Or[lane + 32] = a1;
}

// ---------------------------------------------------------------------------
// Launch
// ---------------------------------------------------------------------------
static float* sym_addr(const void* sym)
{
    void* p = nullptr;
    cudaGetSymbolAddress(&p, sym);
    return (float*)p;
}

extern "C" void kernel_launch(void* const* d_in, const int* in_sizes, int n_in,
                              void* d_out, int out_size)
{
    const float* x      = (const float*)d_in[0];
    const float* w_qkv  = (const float*)d_in[1];
    const float* b_qkv  = (const float*)d_in[2];
    const float* w_proj = (const float*)d_in[3];
    const float* b_proj = (const float*)d_in[4];

    float* qkv = sym_addr(g_qkv);
    float* ao  = sym_addr(g_ao);

    const size_t OUT_N  = (size_t)Bb * Ss * Ee;
    const size_t ATTN_N = (size_t)Bb * Hh * Ss * Ss;

    float* out = (float*)d_out;
    float* P;
    float* mainOut;
    if ((size_t)out_size >= OUT_N + ATTN_N) {
        mainOut = out;
        P = out + OUT_N;
    } else if ((size_t)out_size == ATTN_N) {
        mainOut = sym_addr(g_spill);
        P = out;
    } else {
        mainOut = out;
        P = sym_addr(g_P);
    }

    const int smemN = G1_SMEM_N * sizeof(float);   // 104448
    const int smemT = G1_SMEM_T * sizeof(float);   // 110592
    cudaFuncSetAttribute(gemm_qk3_kernel,
                         cudaFuncAttributeMaxDynamicSharedMemorySize, smemN);
    cudaFuncSetAttribute(gemm_qkt_kernel,
                         cudaFuncAttributeMaxDynamicSharedMemorySize, smemT);
    cudaFuncSetAttribute(gemm_x1_kernel,
                         cudaFuncAttributeMaxDynamicSharedMemorySize, smemN);

    // 1. QK projection: [4096,1024] @ [1024,2048] + bias (tf32x3 — feeds mask)
    {
        dim3 grid(2048 / 128, MROWS / 128, 1);
        gemm_qk3_kernel<<<grid, 128, smemN>>>(x, w_qkv, b_qkv, qkv);
    }
    // 2. V projection: [4096,1024] @ [1024,1024] + bias (tf32x1, 256 threads)
    {
        dim3 grid(1024 / 128, MROWS / 128, 1);
        gemm_x1_kernel<<<grid, 256, smemN>>>(
            x, w_qkv + 2048, b_qkv + 2048, qkv + 2048, Ee, Ee, QKVN, QKVN);
    }
    // 3. QK^T logits per (b,h), alpha = Dh^-0.5 (tf32x3)
    {
        dim3 grid(Ss / 128, Ss / 128, Bb * Hh);
        gemm_qkt_kernel<<<grid, 128, smemT>>>(qkv, P);
    }
    // 4. warp-per-row softmax + mask + renorm + fused sparse AV
    softmax_av_kernel<<<NROWS / 8, 256>>>(P, qkv, ao);
    // 5. output projection: [4096,1024] @ [1024,1024] + bias (tf32x1, 256 thr)
    {
        dim3 grid(Ee / 128, MROWS / 128, 1);
        gemm_x1_kernel<<<grid, 256, smemN>>>(
            ao, w_proj, b_proj, mainOut, Ee, Ee, Ee, Ee);
    }
}